// round 16
// baseline (speedup 1.0000x reference)
#include <cuda_runtime.h>
#include <math.h>
#include <stdint.h>

#define B_    4096
#define MROWS (B_ * 128)   // 524288

// ---------------- global scratch (aliased; ~1.0GB) ----------------
__device__ float g_qkv[(size_t)MROWS * 384];    // ALIAS: qkv_pack [row][192] uint2 / ffn_pack [row][128] uint2
__device__ float g_comb[(size_t)B_ * 256];
__device__ float g_mw[(size_t)B_ * 4];
__device__ float g_base[(size_t)B_ * 512];
__device__ uint2 g_h_pack[(size_t)MROWS * 64];     // hi/lo pack IS the residual
__device__ uint2 g_ch1_pack[(size_t)MROWS * 32];
__device__ uint2 g_comb_pack[(size_t)B_ * 128];
__device__ uint2 g_wp[200704];

#define OFF_QKV0 0
#define OFF_QKV1 24576
#define OFF_WO0  49152
#define OFF_WO1  57344
#define OFF_FF10 65536
#define OFF_FF11 81920
#define OFF_FF20 98304
#define OFF_FF21 114688
#define OFF_CW2  131072
#define OFF_SW1  135168

__device__ __forceinline__ float siluf(float x) { return x / (1.f + __expf(-x)); }
__device__ __forceinline__ float tanh_fast(float x) { return 1.f - 2.f / (__expf(2.f * x) + 1.f); }
__device__ __forceinline__ uint32_t smem_u32(const void* p) {
    uint32_t a;
    asm("{ .reg .u64 t; cvta.to.shared.u64 t, %1; cvt.u32.u64 %0, t; }" : "=r"(a) : "l"(p));
    return a;
}
__device__ __forceinline__ uint2 pack_bf16_pair(float v0, float v1) {
    uint32_t hi;
    asm("cvt.rn.bf16x2.f32 %0, %1, %2;" : "=r"(hi) : "f"(v1), "f"(v0));
    float b0 = __uint_as_float(hi << 16);
    float b1 = __uint_as_float(hi & 0xffff0000u);
    uint32_t lo;
    asm("cvt.rn.bf16x2.f32 %0, %1, %2;" : "=r"(lo) : "f"(v1 - b1), "f"(v0 - b0));
    return make_uint2(hi, lo);
}
__device__ __forceinline__ float2 unpack_pair(uint2 v) {
    float2 r;
    r.x = __uint_as_float(v.x << 16) + __uint_as_float(v.y << 16);
    r.y = __uint_as_float(v.x & 0xffff0000u) + __uint_as_float(v.y & 0xffff0000u);
    return r;
}
__device__ __forceinline__ void cp16(uint32_t dst, const void* src) {
    asm volatile("cp.async.ca.shared.global [%0], [%1], 16;" :: "r"(dst), "l"(src));
}
__device__ __forceinline__ void cp_commit() { asm volatile("cp.async.commit_group;" ::: "memory"); }
template <int N>
__device__ __forceinline__ void cp_wait() { asm volatile("cp.async.wait_group %0;" :: "n"(N) : "memory"); }
__device__ __forceinline__ void mma16(float* c, const uint32_t* a, uint32_t b0, uint32_t b1) {
    asm volatile(
        "mma.sync.aligned.m16n8k16.row.col.f32.bf16.bf16.f32 "
        "{%0,%1,%2,%3}, {%4,%5,%6,%7}, {%8,%9}, {%0,%1,%2,%3};"
        : "+f"(c[0]), "+f"(c[1]), "+f"(c[2]), "+f"(c[3])
        : "r"(a[0]), "r"(a[1]), "r"(a[2]), "r"(a[3]), "r"(b0), "r"(b1));
}

// ---------------- merged weight pre-pack (single launch) ----------------
__device__ __forceinline__ void pack_seg(const float* __restrict__ W, uint2* __restrict__ dst,
                                         int K, int N, int idx) {
    int kp2 = K >> 1;
    int n = idx / kp2, kp = idx - n * kp2;
    int chunk = n >> 7, nn = n & 127;
    dst[((size_t)chunk * 128 + nn) * kp2 + kp] =
        pack_bf16_pair(W[(size_t)(2 * kp) * N + n], W[(size_t)(2 * kp + 1) * N + n]);
}
__global__ void __launch_bounds__(256) pack_all(const float* __restrict__ wqkv,
                                                const float* __restrict__ wo,
                                                const float* __restrict__ ffw1,
                                                const float* __restrict__ ffw2,
                                                const float* __restrict__ cw2,
                                                const float* __restrict__ sw1,
                                                uint2* __restrict__ gw) {
    int idx = blockIdx.x * 256 + threadIdx.x;
    if (idx < 49152) {
        int l = idx / 24576, r = idx - l * 24576;
        pack_seg(wqkv + (size_t)l * 49152, gw + (l ? OFF_QKV1 : OFF_QKV0), 128, 384, r);
    } else if (idx < 65536) {
        int r = idx - 49152;
        int l = r / 8192; r -= l * 8192;
        pack_seg(wo + (size_t)l * 16384, gw + (l ? OFF_WO1 : OFF_WO0), 128, 128, r);
    } else if (idx < 98304) {
        int r = idx - 65536;
        int l = r / 16384; r -= l * 16384;
        pack_seg(ffw1 + (size_t)l * 32768, gw + (l ? OFF_FF11 : OFF_FF10), 128, 256, r);
    } else if (idx < 131072) {
        int r = idx - 98304;
        int l = r / 16384; r -= l * 16384;
        pack_seg(ffw2 + (size_t)l * 32768, gw + (l ? OFF_FF21 : OFF_FF20), 256, 128, r);
    } else if (idx < 135168) {
        pack_seg(cw2, gw + OFF_CW2, 64, 128, idx - 131072);
    } else if (idx < 200704) {
        int r = idx - 135168;
        int n = r / 128, kp = r - (r / 128) * 128;
        int chunk = n >> 7, nn = n & 127;
        float v0 = sw1[((size_t)(n >> 7) * 258 + 2 + 2 * kp) * 128 + nn];
        float v1 = sw1[((size_t)(n >> 7) * 258 + 2 + 2 * kp + 1) * 128 + nn];
        gw[OFF_SW1 + ((size_t)chunk * 128 + nn) * 128 + kp] = pack_bf16_pair(v0, v1);
    }
}

// ---------------- streaming bf16 2-term GEMM ----------------
// MODE: 0 bias fp32-only, 1 relu pack-only, 2 res(pack)+LN pack-only, 3 silu pack-only, 5 bias pack-only
#define RS 20
#define TBUF 20480
#define TG_SMEM (4 * TBUF)
template <int MODE>
__global__ void __launch_bounds__(128, 2) tgemm(const uint2* __restrict__ Apack,
                                                const uint2* __restrict__ Bpack,
                                                int Ktot,
                                                const float* __restrict__ bias,
                                                const uint2* __restrict__ respack,
                                                const float* __restrict__ gma,
                                                const float* __restrict__ bta,
                                                float* __restrict__ C, int ldc,
                                                uint2* __restrict__ Cpack, int ldcp) {
    extern __shared__ char dsm[];
    const uint32_t sbase = smem_u32(dsm);
    const int t = threadIdx.x;
    const int w = t >> 5, lane = t & 31;
    const int g = lane >> 2, t4 = lane & 3;
    const int bn = blockIdx.x * 128, bm = blockIdx.y * 128;
    const int wrow = w * 32;
    const int kpTot = Ktot >> 1;

    float acc0[16][4], acc1[16][4];
#pragma unroll
    for (int j = 0; j < 16; j++)
#pragma unroll
        for (int q = 0; q < 4; q++) { acc0[j][q] = 0.f; acc1[j][q] = 0.f; }

    const int P = Ktot >> 5;
    const uint2* Bbase = Bpack + (size_t)blockIdx.x * 128 * kpTot;
    const int srow = t >> 3, sj = t & 7;

#pragma unroll
    for (int i = 0; i < 8; i++) {
        int row = srow + i * 16;
        cp16(sbase + (uint32_t)(row * RS * 8 + sj * 16),
             Apack + (size_t)(bm + row) * kpTot + sj * 2);
        cp16(sbase + (uint32_t)(2 * TBUF + row * RS * 8 + sj * 16),
             Bbase + (size_t)row * kpTot + sj * 2);
    }
    cp_commit();

    for (int p = 0; p < P; p++) {
        const bool more = (p + 1 < P);
        if (more) {
            const int buf = (p + 1) & 1;
            const int kpo = (p + 1) * 16;
#pragma unroll
            for (int i = 0; i < 8; i++) {
                int row = srow + i * 16;
                cp16(sbase + (uint32_t)(buf * TBUF + row * RS * 8 + sj * 16),
                     Apack + (size_t)(bm + row) * kpTot + kpo + sj * 2);
                cp16(sbase + (uint32_t)(2 * TBUF + buf * TBUF + row * RS * 8 + sj * 16),
                     Bbase + (size_t)row * kpTot + kpo + sj * 2);
            }
            cp_commit();
            cp_wait<1>();
        } else {
            cp_wait<0>();
        }
        __syncthreads();

        const uint2* As = (const uint2*)(dsm + (p & 1) * TBUF);
        const uint2* Bs = (const uint2*)(dsm + 2 * TBUF + (p & 1) * TBUF);
#pragma unroll
        for (int h2 = 0; h2 < 2; h2++) {
            const int kb = h2 * 8;
            const int r = wrow + g;
            uint32_t a0h[4], a0l[4], a1h[4], a1l[4];
            uint2 q;
            q = As[(r) * RS + kb + t4];          a0h[0] = q.x; a0l[0] = q.y;
            q = As[(r + 8) * RS + kb + t4];      a0h[1] = q.x; a0l[1] = q.y;
            q = As[(r) * RS + kb + t4 + 4];      a0h[2] = q.x; a0l[2] = q.y;
            q = As[(r + 8) * RS + kb + t4 + 4];  a0h[3] = q.x; a0l[3] = q.y;
            q = As[(r + 16) * RS + kb + t4];     a1h[0] = q.x; a1l[0] = q.y;
            q = As[(r + 24) * RS + kb + t4];     a1h[1] = q.x; a1l[1] = q.y;
            q = As[(r + 16) * RS + kb + t4 + 4]; a1h[2] = q.x; a1l[2] = q.y;
            q = As[(r + 24) * RS + kb + t4 + 4]; a1h[3] = q.x; a1l[3] = q.y;
#pragma unroll
            for (int j = 0; j < 16; j++) {
                uint2 b0 = Bs[(j * 8 + g) * RS + kb + t4];
                uint2 b1 = Bs[(j * 8 + g) * RS + kb + t4 + 4];
                mma16(acc0[j], a0h, b0.x, b1.x);
                mma16(acc0[j], a0l, b0.x, b1.x);
                mma16(acc0[j], a0h, b0.y, b1.y);
                mma16(acc1[j], a1h, b0.x, b1.x);
                mma16(acc1[j], a1l, b0.x, b1.x);
                mma16(acc1[j], a1h, b0.y, b1.y);
            }
        }
        __syncthreads();
    }

    float2 bias2[16];
#pragma unroll
    for (int j = 0; j < 16; j++) bias2[j] = *(const float2*)(bias + bn + j * 8 + 2 * t4);

    if (MODE == 2) {
#pragma unroll
        for (int i = 0; i < 2; i++) {
            float (*ac)[4] = i ? acc1 : acc0;
#pragma unroll
            for (int h = 0; h < 2; h++) {
                const int row = bm + wrow + i * 16 + h * 8 + g;
                const uint2* rp = respack + (size_t)row * 64 + t4;
                float sum = 0.f;
#pragma unroll
                for (int j = 0; j < 16; j++) {
                    float2 rv = unpack_pair(rp[4 * j]);
                    float v0 = ac[j][2 * h] + bias2[j].x + rv.x;
                    float v1 = ac[j][2 * h + 1] + bias2[j].y + rv.y;
                    ac[j][2 * h] = v0;
                    ac[j][2 * h + 1] = v1;
                    sum += v0 + v1;
                }
                sum += __shfl_xor_sync(0xffffffffu, sum, 1);
                sum += __shfl_xor_sync(0xffffffffu, sum, 2);
                const float mean = sum * (1.f / 128.f);
                float var = 0.f;
#pragma unroll
                for (int j = 0; j < 16; j++) {
                    float v0 = ac[j][2 * h] - mean;
                    float v1 = ac[j][2 * h + 1] - mean;
                    ac[j][2 * h] = v0;
                    ac[j][2 * h + 1] = v1;
                    var += v0 * v0 + v1 * v1;
                }
                var += __shfl_xor_sync(0xffffffffu, var, 1);
                var += __shfl_xor_sync(0xffffffffu, var, 2);
                const float rs = rsqrtf(var * (1.f / 128.f) + 1e-5f);
                uint2* pp = Cpack + (size_t)row * ldcp + t4;
#pragma unroll
                for (int j = 0; j < 16; j++) {
                    float2 gv = *(const float2*)(gma + j * 8 + 2 * t4);
                    float2 tv = *(const float2*)(bta + j * 8 + 2 * t4);
                    float o0 = fmaf(gv.x, ac[j][2 * h] * rs, tv.x);
                    float o1 = fmaf(gv.y, ac[j][2 * h + 1] * rs, tv.y);
                    pp[4 * j] = pack_bf16_pair(o0, o1);
                }
            }
        }
    } else {
#pragma unroll
        for (int i = 0; i < 2; i++) {
            float (*ac)[4] = i ? acc1 : acc0;
#pragma unroll
            for (int h = 0; h < 2; h++) {
                const int row = bm + wrow + i * 16 + h * 8 + g;
                float* cp = (MODE == 0) ? (C + (size_t)row * ldc + bn + 2 * t4) : nullptr;
                uint2* pp = (MODE != 0) ? (Cpack + (size_t)row * ldcp + (bn >> 1) + t4) : nullptr;
#pragma unroll
                for (int j = 0; j < 16; j++) {
                    float o0 = ac[j][2 * h] + bias2[j].x;
                    float o1 = ac[j][2 * h + 1] + bias2[j].y;
                    if (MODE == 1) { o0 = fmaxf(o0, 0.f); o1 = fmaxf(o1, 0.f); }
                    if (MODE == 3) { o0 = siluf(o0); o1 = siluf(o1); }
                    if (MODE == 0) { cp[j * 8] = o0; cp[j * 8 + 1] = o1; }
                    else pp[4 * j] = pack_bf16_pair(o0, o1);
                }
            }
        }
    }
}

// ---------------- fused attention + o-proj + res + LN ----------------
// per-batch CTA, 256 threads (8 warps), regions: A=Q/O, B=K(V staging)/Wo staging, C=Vt
#define FRS 68
#define FREG (128 * FRS * 8)        // 69632 bytes
#define ATTNF_SMEM (3 * FREG)       // 208896
__global__ void __launch_bounds__(256, 1) attn_fused(const uint2* __restrict__ qkvp,
                                                     const uint2* __restrict__ wop,
                                                     const float* __restrict__ bo,
                                                     uint2* __restrict__ hpack,
                                                     const float* __restrict__ gma,
                                                     const float* __restrict__ bta) {
    extern __shared__ char sm[];
    const uint32_t sb = smem_u32(sm);
    uint2* Ar = (uint2*)sm;                    // Q, later O
    uint2* Br = (uint2*)(sm + FREG);           // V staging, K, later Wo staging
    uint2* Ct = (uint2*)(sm + 2 * FREG);       // Vt
    const int b = blockIdx.x;
    const int t = threadIdx.x, w = t >> 5, lane = t & 31;
    const int g = lane >> 2, t4 = lane & 3;
    const int r = w * 16 + g;                  // warp row base (16-row warp tile)
    const uint2* base = qkvp + (size_t)(b * 128) * 192;

    // --- phase 0a: stage V into region B ---
    for (int idx = t; idx < 4096; idx += 256) {
        int row = idx >> 5, c = (idx & 31) * 2;
        cp16(sb + FREG + (uint32_t)(row * FRS + c) * 8u, base + (size_t)row * 192 + 128 + c);
    }
    cp_commit();
    cp_wait<0>();
    __syncthreads();
    // --- phase 0b: transpose V -> Vt in region C ---
    for (int e = t; e < 128 * 64; e += 256) {
        int d = e >> 6, kp = e & 63;
        uint2 p0 = Br[(2 * kp) * FRS + (d >> 1)];
        uint2 p1 = Br[(2 * kp + 1) * FRS + (d >> 1)];
        float v0, v1;
        if (d & 1) {
            v0 = __uint_as_float(p0.x & 0xffff0000u) + __uint_as_float(p0.y & 0xffff0000u);
            v1 = __uint_as_float(p1.x & 0xffff0000u) + __uint_as_float(p1.y & 0xffff0000u);
        } else {
            v0 = __uint_as_float(p0.x << 16) + __uint_as_float(p0.y << 16);
            v1 = __uint_as_float(p1.x << 16) + __uint_as_float(p1.y << 16);
        }
        Ct[d * FRS + kp] = pack_bf16_pair(v0, v1);
    }
    __syncthreads();
    // --- phase 0c: stage Q into A, K into B (overwrites V staging) ---
    for (int idx = t; idx < 4096; idx += 256) {
        int row = idx >> 5, c = (idx & 31) * 2;
        cp16(sb + (uint32_t)(row * FRS + c) * 8u, base + (size_t)row * 192 + c);
        cp16(sb + FREG + (uint32_t)(row * FRS + c) * 8u, base + (size_t)row * 192 + 64 + c);
    }
    cp_commit();
    cp_wait<0>();
    __syncthreads();

    // --- phase 1: attention, 4 heads, warp = 16 rows ---
    const float cs = 0.17677669529663687f;
    float O[4][4][4];
#pragma unroll
    for (int h = 0; h < 4; h++)
#pragma unroll
        for (int j = 0; j < 4; j++)
#pragma unroll
            for (int q = 0; q < 4; q++) O[h][j][q] = 0.f;

#pragma unroll
    for (int h = 0; h < 4; h++) {
        float s[16][4];
#pragma unroll
        for (int j = 0; j < 16; j++)
#pragma unroll
            for (int q = 0; q < 4; q++) s[j][q] = 0.f;
#pragma unroll
        for (int h2 = 0; h2 < 2; h2++) {
            const int kb = h * 16 + h2 * 8;
            uint32_t ah[4], al[4];
            uint2 qv;
            qv = Ar[r * FRS + kb + t4];           ah[0] = qv.x; al[0] = qv.y;
            qv = Ar[(r + 8) * FRS + kb + t4];     ah[1] = qv.x; al[1] = qv.y;
            qv = Ar[r * FRS + kb + t4 + 4];       ah[2] = qv.x; al[2] = qv.y;
            qv = Ar[(r + 8) * FRS + kb + t4 + 4]; ah[3] = qv.x; al[3] = qv.y;
#pragma unroll
            for (int j = 0; j < 16; j++) {
                uint2 b0 = Br[(j * 8 + g) * FRS + kb + t4];
                uint2 b1 = Br[(j * 8 + g) * FRS + kb + t4 + 4];
                mma16(s[j], ah, b0.x, b1.x);
                mma16(s[j], al, b0.x, b1.x);
                mma16(s[j], ah, b0.y, b1.y);
            }
        }
        float m0 = -1e30f, m1 = -1e30f;
#pragma unroll
        for (int j = 0; j < 16; j++) {
            m0 = fmaxf(m0, fmaxf(s[j][0], s[j][1]));
            m1 = fmaxf(m1, fmaxf(s[j][2], s[j][3]));
        }
        m0 = fmaxf(m0, __shfl_xor_sync(0xffffffffu, m0, 1));
        m0 = fmaxf(m0, __shfl_xor_sync(0xffffffffu, m0, 2));
        m1 = fmaxf(m1, __shfl_xor_sync(0xffffffffu, m1, 1));
        m1 = fmaxf(m1, __shfl_xor_sync(0xffffffffu, m1, 2));
        float l0 = 0.f, l1 = 0.f;
#pragma unroll
        for (int j = 0; j < 16; j++) {
            s[j][0] = __expf((s[j][0] - m0) * cs);
            s[j][1] = __expf((s[j][1] - m0) * cs);
            s[j][2] = __expf((s[j][2] - m1) * cs);
            s[j][3] = __expf((s[j][3] - m1) * cs);
            l0 += s[j][0] + s[j][1];
            l1 += s[j][2] + s[j][3];
        }
        l0 += __shfl_xor_sync(0xffffffffu, l0, 1);
        l0 += __shfl_xor_sync(0xffffffffu, l0, 2);
        l1 += __shfl_xor_sync(0xffffffffu, l1, 1);
        l1 += __shfl_xor_sync(0xffffffffu, l1, 2);
        const float li0 = 1.f / l0, li1 = 1.f / l1;
#pragma unroll
        for (int kc = 0; kc < 8; kc++) {
            uint32_t ph[4], pl[4];
            uint2 u;
            u = pack_bf16_pair(s[2 * kc][0], s[2 * kc][1]);         ph[0] = u.x; pl[0] = u.y;
            u = pack_bf16_pair(s[2 * kc][2], s[2 * kc][3]);         ph[1] = u.x; pl[1] = u.y;
            u = pack_bf16_pair(s[2 * kc + 1][0], s[2 * kc + 1][1]); ph[2] = u.x; pl[2] = u.y;
            u = pack_bf16_pair(s[2 * kc + 1][2], s[2 * kc + 1][3]); ph[3] = u.x; pl[3] = u.y;
#pragma unroll
            for (int j = 0; j < 4; j++) {
                uint2 b0 = Ct[(h * 32 + j * 8 + g) * FRS + kc * 8 + t4];
                uint2 b1 = Ct[(h * 32 + j * 8 + g) * FRS + kc * 8 + t4 + 4];
                mma16(O[h][j], ph, b0.x, b1.x);
                mma16(O[h][j], pl, b0.x, b1.x);
                mma16(O[h][j], ph, b0.y, b1.y);
            }
        }
#pragma unroll
        for (int j = 0; j < 4; j++) {
            O[h][j][0] *= li0; O[h][j][1] *= li0;
            O[h][j][2] *= li1; O[h][j][3] *= li1;
        }
    }
    __syncthreads();   // all warps done reading Q region
    // write O packed into region A
#pragma unroll
    for (int h = 0; h < 4; h++)
#pragma unroll
        for (int j = 0; j < 4; j++) {
            Ar[r * FRS + h * 16 + j * 4 + t4] = pack_bf16_pair(O[h][j][0], O[h][j][1]);
            Ar[(r + 8) * FRS + h * 16 + j * 4 + t4] = pack_bf16_pair(O[h][j][2], O[h][j][3]);
        }
    __syncthreads();

    // --- phase 2: o-proj GEMM (K=128, N=128) + residual + LN ---
    float acc[16][4];
#pragma unroll
    for (int j = 0; j < 16; j++)
#pragma unroll
        for (int q = 0; q < 4; q++) acc[j][q] = 0.f;
    const int srow = t >> 3, sj = t & 7;
    // stage Wo slice p=0 into region B buf0
#pragma unroll
    for (int i = 0; i < 4; i++) {
        int row = srow + i * 32;
        cp16(sb + FREG + (uint32_t)(row * RS * 8 + sj * 16), wop + (size_t)row * 64 + sj * 2);
    }
    cp_commit();
    for (int p = 0; p < 4; p++) {
        const bool more = (p + 1 < 4);
        if (more) {
            const int buf = (p + 1) & 1;
            const int kpo = (p + 1) * 16;
#pragma unroll
            for (int i = 0; i < 4; i++) {
                int row = srow + i * 32;
                cp16(sb + FREG + (uint32_t)(buf * TBUF + row * RS * 8 + sj * 16),
                     wop + (size_t)row * 64 + kpo + sj * 2);
            }
            cp_commit();
            cp_wait<1>();
        } else {
            cp_wait<0>();
        }
        __syncthreads();
        const uint2* Bs = (const uint2*)(sm + FREG + (p & 1) * TBUF);
#pragma unroll
        for (int h2 = 0; h2 < 2; h2++) {
            const int ka = p * 16 + h2 * 8;   // A kp offset
            const int kb = h2 * 8;            // B staged kp offset
            uint32_t ah[4], al[4];
            uint2 qv;
            qv = Ar[r * FRS + ka + t4];           ah[0] = qv.x; al[0] = qv.y;
            qv = Ar[(r + 8) * FRS + ka + t4];     ah[1] = qv.x; al[1] = qv.y;
            qv = Ar[r * FRS + ka + t4 + 4];       ah[2] = qv.x; al[2] = qv.y;
            qv = Ar[(r + 8) * FRS + ka + t4 + 4]; ah[3] = qv.x; al[3] = qv.y;
#pragma unroll
            for (int j = 0; j < 16; j++) {
                uint2 b0 = Bs[(j * 8 + g) * RS + kb + t4];
                uint2 b1 = Bs[(j * 8 + g) * RS + kb + t4 + 4];
                mma16(acc[j], ah, b0.x, b1.x);
                mma16(acc[j], al, b0.x, b1.x);
                mma16(acc[j], ah, b0.y, b1.y);
            }
        }
        __syncthreads();
    }
    // epilogue: bias + residual(pack) + LN -> hpack
    float2 bias2[16];
#pragma unroll
    for (int j = 0; j < 16; j++) bias2[j] = *(const float2*)(bo + j * 8 + 2 * t4);
#pragma unroll
    for (int h = 0; h < 2; h++) {
        const int row = b * 128 + w * 16 + h * 8 + g;
        const uint2* rp = hpack + (size_t)row * 64 + t4;
        float sum = 0.f;
#pragma unroll
        for (int j = 0; j < 16; j++) {
            float2 rv = unpack_pair(rp[4 * j]);
            float v0 = acc[j][2 * h] + bias2[j].x + rv.x;
            float v1 = acc[j][2 * h + 1] + bias2[j].y + rv.y;
            acc[j][2 * h] = v0;
            acc[j][2 * h + 1] = v1;
            sum += v0 + v1;
        }
        sum += __shfl_xor_sync(0xffffffffu, sum, 1);
        sum += __shfl_xor_sync(0xffffffffu, sum, 2);
        const float mean = sum * (1.f / 128.f);
        float var = 0.f;
#pragma unroll
        for (int j = 0; j < 16; j++) {
            float v0 = acc[j][2 * h] - mean;
            float v1 = acc[j][2 * h + 1] - mean;
            acc[j][2 * h] = v0;
            acc[j][2 * h + 1] = v1;
            var += v0 * v0 + v1 * v1;
        }
        var += __shfl_xor_sync(0xffffffffu, var, 1);
        var += __shfl_xor_sync(0xffffffffu, var, 2);
        const float rsq = rsqrtf(var * (1.f / 128.f) + 1e-5f);
        uint2* pp = hpack + (size_t)row * 64 + t4;
#pragma unroll
        for (int j = 0; j < 16; j++) {
            float2 gv = *(const float2*)(gma + j * 8 + 2 * t4);
            float2 tv = *(const float2*)(bta + j * 8 + 2 * t4);
            float o0 = fmaf(gv.x, acc[j][2 * h] * rsq, tv.x);
            float o1 = fmaf(gv.y, acc[j][2 * h + 1] * rsq, tv.y);
            pp[4 * j] = pack_bf16_pair(o0, o1);
        }
    }
}

// ---------------- time embedding ----------------
__global__ void __launch_bounds__(256) time_kernel(const int* __restrict__ ts,
                                                   const float* __restrict__ w1,
                                                   const float* __restrict__ b1,
                                                   const float* __restrict__ w2,
                                                   const float* __restrict__ b2) {
    __shared__ float te[128];
    __shared__ float hid[256];
    __shared__ float tout[128];
    const int b = blockIdx.x, t = threadIdx.x;
    const float tf = (float)ts[b];
    if (t < 128) {
        int i = t & 63;
        float freq = expf(-0.14391156831212787f * (float)i);
        float arg = tf * freq;
        te[t] = (t < 64) ? cosf(arg) : sinf(arg);
    }
    __syncthreads();
    float a = b1[t];
    for (int i = 0; i < 128; i++) a = fmaf(te[i], w1[i * 256 + t], a);
    hid[t] = siluf(a);
    __syncthreads();
    if (t < 128) {
        float a2 = b2[t];
        for (int i = 0; i < 256; i++) a2 = fmaf(hid[i], w2[i * 128 + t], a2);
        g_comb[(size_t)b * 256 + t] = a2;
        tout[t] = a2;
    }
    __syncthreads();
    if (t < 64) g_comb_pack[(size_t)b * 128 + t] = pack_bf16_pair(tout[2 * t], tout[2 * t + 1]);
}

// ---------------- cond layer1 -> packed ----------------
__global__ void __launch_bounds__(256) condh1_kernel(const float* __restrict__ cond,
                                                     const float* __restrict__ w1,
                                                     const float* __restrict__ b1,
                                                     uint2* __restrict__ outp) {
    const size_t row = (size_t)blockIdx.x * 32 + (threadIdx.x >> 3);
    const int dg = threadIdx.x & 7;
    const float* cp = cond + row * 6;
    float c0 = cp[0], c1 = cp[1], c2 = cp[2], c3 = cp[3], c4 = cp[4], c5 = cp[5];
    float o[8];
#pragma unroll
    for (int j = 0; j < 8; j++) {
        int dd = dg * 8 + j;
        float a = b1[dd];
        a = fmaf(c0, w1[0 * 64 + dd], a);
        a = fmaf(c1, w1[1 * 64 + dd], a);
        a = fmaf(c2, w1[2 * 64 + dd], a);
        a = fmaf(c3, w1[3 * 64 + dd], a);
        a = fmaf(c4, w1[4 * 64 + dd], a);
        a = fmaf(c5, w1[5 * 64 + dd], a);
        o[j] = siluf(a);
    }
#pragma unroll
    for (int i = 0; i < 4; i++)
        outp[row * 32 + dg * 4 + i] = pack_bf16_pair(o[2 * i], o[2 * i + 1]);
}

// ---------------- mean pool (reads pack) ----------------
__global__ void __launch_bounds__(128) pool_kernel() {
    __shared__ float buf[128];
    const int b = blockIdx.x, d = threadIdx.x;
    const uint2* p = g_h_pack + (size_t)b * 128 * 64 + (d >> 1);
    float s = 0.f;
    if (d & 1) {
        for (int j = 0; j < 128; j++) {
            uint2 v = p[(size_t)j * 64];
            s += __uint_as_float(v.x & 0xffff0000u) + __uint_as_float(v.y & 0xffff0000u);
        }
    } else {
        for (int j = 0; j < 128; j++) {
            uint2 v = p[(size_t)j * 64];
            s += __uint_as_float(v.x << 16) + __uint_as_float(v.y << 16);
        }
    }
    s *= (1.f / 128.f);
    g_comb[(size_t)b * 256 + 128 + d] = s;
    buf[d] = s;
    __syncthreads();
    if (d < 64) g_comb_pack[(size_t)b * 128 + 64 + d] = pack_bf16_pair(buf[2 * d], buf[2 * d + 1]);
}

// ---------------- mixture weights ----------------
__global__ void __launch_bounds__(128) mw_kernel(const float* __restrict__ w1,
                                                 const float* __restrict__ b1,
                                                 const float* __restrict__ w2,
                                                 const float* __restrict__ b2) {
    __shared__ float scm[256];
    __shared__ float hid[128];
    __shared__ float lg[4];
    const int b = blockIdx.x, t = threadIdx.x;
    scm[t] = g_comb[(size_t)b * 256 + t];
    scm[128 + t] = g_comb[(size_t)b * 256 + 128 + t];
    __syncthreads();
    float a = b1[t];
    for (int i = 0; i < 256; i++) a = fmaf(scm[i], w1[i * 128 + t], a);
    hid[t] = siluf(a);
    __syncthreads();
    if (t < 4) {
        float a2 = b2[t];
        for (int j = 0; j < 128; j++) a2 = fmaf(hid[j], w2[j * 4 + t], a2);
        lg[t] = a2;
    }
    __syncthreads();
    if (t == 0) {
        float mm = fmaxf(fmaxf(lg[0], lg[1]), fmaxf(lg[2], lg[3]));
        float e0 = __expf(lg[0] - mm), e1 = __expf(lg[1] - mm);
        float e2 = __expf(lg[2] - mm), e3 = __expf(lg[3] - mm);
        float inv = 1.f / (e0 + e1 + e2 + e3);
        g_mw[(size_t)b * 4 + 0] = e0 * inv;
        g_mw[(size_t)b * 4 + 1] = e1 * inv;
        g_mw[(size_t)b * 4 + 2] = e2 * inv;
        g_mw[(size_t)b * 4 + 3] = e3 * inv;
    }
}

// ---------------- students ----------------
__global__ void __launch_bounds__(128) student_kernel(const float* __restrict__ x,
                                                      const float* __restrict__ sw1,
                                                      const float* __restrict__ sw2,
                                                      const float* __restrict__ sb2,
                                                      float* __restrict__ out) {
    __shared__ float sb[512], w0[512], w1s[512], s2a[512], s2b[512];
    __shared__ float smw[4], sbias2[8];
    const int b = blockIdx.x, t = threadIdx.x;
    for (int i = t; i < 512; i += 128) {
        sb[i] = g_base[(size_t)b * 512 + i];
        int k = i >> 7, j = i & 127;
        w0[i] = sw1[((size_t)k * 258 + 0) * 128 + j];
        w1s[i] = sw1[((size_t)k * 258 + 1) * 128 + j];
        s2a[i] = sw2[i * 2 + 0];
        s2b[i] = sw2[i * 2 + 1];
    }
    if (t < 4) smw[t] = g_mw[(size_t)b * 4 + t];
    if (t < 8) sbias2[t] = sb2[t];
    __syncthreads();
    const float x0 = x[(size_t)b * 256 + t];
    const float x1 = x[(size_t)b * 256 + 128 + t];
    float o0 = 0.f, o1 = 0.f;
#pragma unroll
    for (int k = 0; k < 4; k++) {
        float a0 = 0.f, a1 = 0.f;
        for (int j = 0; j < 128; j++) {
            int idx = k * 128 + j;
            float hv = tanh_fast(fmaf(x1, w1s[idx], fmaf(x0, w0[idx], sb[idx])));
            a0 = fmaf(hv, s2a[idx], a0);
            a1 = fmaf(hv, s2b[idx], a1);
        }
        float wk = smw[k];
        o0 = fmaf(wk, a0 + sbias2[k * 2 + 0], o0);
        o1 = fmaf(wk, a1 + sbias2[k * 2 + 1], o1);
    }
    out[(size_t)b * 256 + t] = o0;
    out[(size_t)b * 256 + 128 + t] = o1;
}

// ---------------- launcher ----------------
extern "C" void kernel_launch(void* const* d_in, const int* in_sizes, int n_in,
                              void* d_out, int out_size) {
    const float* x    = (const float*)d_in[0];
    const int*   ts   = (const int*)d_in[1];
    const float* cond = (const float*)d_in[2];
    const float* t_w1 = (const float*)d_in[3];
    const float* t_b1 = (const float*)d_in[4];
    const float* t_w2 = (const float*)d_in[5];
    const float* t_b2 = (const float*)d_in[6];
    const float* c_w1 = (const float*)d_in[7];
    const float* c_b1 = (const float*)d_in[8];
    const float* c_w2 = (const float*)d_in[9];
    const float* c_b2 = (const float*)d_in[10];
    const float* wqkv = (const float*)d_in[11];
    const float* bqkv = (const float*)d_in[12];
    const float* wo   = (const float*)d_in[13];
    const float* bo   = (const float*)d_in[14];
    const float* ln1g = (const float*)d_in[15];
    const float* ln1b = (const float*)d_in[16];
    const float* ffw1 = (const float*)d_in[17];
    const float* ffb1 = (const float*)d_in[18];
    const float* ffw2 = (const float*)d_in[19];
    const float* ffb2 = (const float*)d_in[20];
    const float* ln2g = (const float*)d_in[21];
    const float* ln2b = (const float*)d_in[22];
    const float* mww1 = (const float*)d_in[23];
    const float* mwb1 = (const float*)d_in[24];
    const float* mww2 = (const float*)d_in[25];
    const float* mwb2 = (const float*)d_in[26];
    const float* sw1  = (const float*)d_in[27];
    const float* sb1  = (const float*)d_in[28];
    const float* sw2  = (const float*)d_in[29];
    const float* sb2  = (const float*)d_in[30];
    float* out = (float*)d_out;

    float *gqkv, *gcomb, *gbase;
    uint2 *ghp, *gcp, *gcmb, *gw;
    cudaGetSymbolAddress((void**)&gqkv, g_qkv);
    cudaGetSymbolAddress((void**)&gcomb, g_comb);
    cudaGetSymbolAddress((void**)&gbase, g_base);
    cudaGetSymbolAddress((void**)&ghp, g_h_pack);
    cudaGetSymbolAddress((void**)&gcp, g_ch1_pack);
    cudaGetSymbolAddress((void**)&gcmb, g_comb_pack);
    cudaGetSymbolAddress((void**)&gw, g_wp);
    uint2* gqp = (uint2*)gqkv;   // qkv pack [row][192]
    uint2* gfp = (uint2*)gqkv;   // ffn-hidden pack [row][128] (after attn consumed qkv pack)

    cudaFuncSetAttribute(attn_fused, cudaFuncAttributeMaxDynamicSharedMemorySize, ATTNF_SMEM);
    cudaFuncSetAttribute(tgemm<0>, cudaFuncAttributeMaxDynamicSharedMemorySize, TG_SMEM);
    cudaFuncSetAttribute(tgemm<1>, cudaFuncAttributeMaxDynamicSharedMemorySize, TG_SMEM);
    cudaFuncSetAttribute(tgemm<2>, cudaFuncAttributeMaxDynamicSharedMemorySize, TG_SMEM);
    cudaFuncSetAttribute(tgemm<3>, cudaFuncAttributeMaxDynamicSharedMemorySize, TG_SMEM);
    cudaFuncSetAttribute(tgemm<5>, cudaFuncAttributeMaxDynamicSharedMemorySize, TG_SMEM);

    pack_all<<<784, 256>>>(wqkv, wo, ffw1, ffw2, c_w2, sw1, gw);
    time_kernel<<<B_, 256>>>(ts, t_w1, t_b1, t_w2, t_b2);
    condh1_kernel<<<MROWS / 32, 256>>>(cond, c_w1, c_b1, gcp);
    // cond layer2: silu -> ghp (pack only)
    tgemm<3><<<dim3(1, MROWS / 128), 128, TG_SMEM>>>(gcp, gw + OFF_CW2, 64, c_b2,
                                                     nullptr, nullptr, nullptr,
                                                     nullptr, 0, ghp, 64);
    const size_t qkvoff[2] = {OFF_QKV0, OFF_QKV1};
    const size_t wooff[2] = {OFF_WO0, OFF_WO1};
    const size_t f1off[2] = {OFF_FF10, OFF_FF11};
    const size_t f2off[2] = {OFF_FF20, OFF_FF21};
    for (int l = 0; l < 2; l++) {
        // qkv: pack-only output [row][192]
        tgemm<5><<<dim3(3, MROWS / 128), 128, TG_SMEM>>>(ghp, gw + qkvoff[l], 128,
                                                         bqkv + l * 384, nullptr, nullptr,
                                                         nullptr, nullptr, 0, gqp, 192);
        // fused attention + o-proj + residual + LN -> ghp
        attn_fused<<<B_, 256, ATTNF_SMEM>>>(gqp, gw + wooff[l], bo + l * 128, ghp,
                                            ln1g + l * 128, ln1b + l * 128);
        // ffn1 relu -> pack (into dead qkv-pack region)
        tgemm<1><<<dim3(2, MROWS / 128), 128, TG_SMEM>>>(ghp, gw + f1off[l], 128,
                                                         ffb1 + l * 256, nullptr, nullptr,
                                                         nullptr, nullptr, 0, gfp, 128);
        // ffn2 (K=256) + res(pack) + LN -> ghp
        tgemm<2><<<dim3(1, MROWS / 128), 128, TG_SMEM>>>(gfp, gw + f2off[l], 256,
                                                         ffb2 + l * 128, ghp, ln2g + l * 128,
                                                         ln2b + l * 128, nullptr, 0, ghp, 64);
    }
    pool_kernel<<<B_, 128>>>();
    mw_kernel<<<B_, 128>>>(mww1, mwb1, mww2, mwb2);
    tgemm<0><<<dim3(4, B_ / 128), 128, TG_SMEM>>>(gcmb, gw + OFF_SW1, 256, sb1,
                                                  nullptr, nullptr, nullptr,
                                                  gbase, 512, nullptr, 0);
    student_kernel<<<B_, 128>>>(x, sw1, sw2, sb2, out);
}

// round 17
// speedup vs baseline: 1.1749x; 1.1749x over previous
#include <cuda_runtime.h>
#include <math.h>
#include <stdint.h>

#define B_    4096
#define MROWS (B_ * 128)   // 524288

// ---------------- global scratch (aliased; ~1.0GB) ----------------
__device__ float g_qkv[(size_t)MROWS * 384];    // ALIAS: qkv_pack [row][192] uint2 / ffn_pack [row][128] uint2
__device__ float g_comb[(size_t)B_ * 256];
__device__ float g_mw[(size_t)B_ * 4];
__device__ float g_base[(size_t)B_ * 512];
__device__ uint2 g_h_pack[(size_t)MROWS * 64];     // hi/lo pack IS the residual
__device__ uint2 g_attn_pack[(size_t)MROWS * 64];  // ALIAS: ch1_pack
__device__ uint2 g_comb_pack[(size_t)B_ * 128];
__device__ uint2 g_wp[200704];

#define OFF_QKV0 0
#define OFF_QKV1 24576
#define OFF_WO0  49152
#define OFF_WO1  57344
#define OFF_FF10 65536
#define OFF_FF11 81920
#define OFF_FF20 98304
#define OFF_FF21 114688
#define OFF_CW2  131072
#define OFF_SW1  135168

__device__ __forceinline__ float siluf(float x) { return x / (1.f + __expf(-x)); }
__device__ __forceinline__ float tanh_fast(float x) { return 1.f - 2.f / (__expf(2.f * x) + 1.f); }
__device__ __forceinline__ uint32_t smem_u32(const void* p) {
    uint32_t a;
    asm("{ .reg .u64 t; cvta.to.shared.u64 t, %1; cvt.u32.u64 %0, t; }" : "=r"(a) : "l"(p));
    return a;
}
__device__ __forceinline__ uint2 pack_bf16_pair(float v0, float v1) {
    uint32_t hi;
    asm("cvt.rn.bf16x2.f32 %0, %1, %2;" : "=r"(hi) : "f"(v1), "f"(v0));
    float b0 = __uint_as_float(hi << 16);
    float b1 = __uint_as_float(hi & 0xffff0000u);
    uint32_t lo;
    asm("cvt.rn.bf16x2.f32 %0, %1, %2;" : "=r"(lo) : "f"(v1 - b1), "f"(v0 - b0));
    return make_uint2(hi, lo);
}
__device__ __forceinline__ float2 unpack_pair(uint2 v) {
    float2 r;
    r.x = __uint_as_float(v.x << 16) + __uint_as_float(v.y << 16);
    r.y = __uint_as_float(v.x & 0xffff0000u) + __uint_as_float(v.y & 0xffff0000u);
    return r;
}
__device__ __forceinline__ void cp16(uint32_t dst, const void* src) {
    asm volatile("cp.async.ca.shared.global [%0], [%1], 16;" :: "r"(dst), "l"(src));
}
__device__ __forceinline__ void cp_commit() { asm volatile("cp.async.commit_group;" ::: "memory"); }
template <int N>
__device__ __forceinline__ void cp_wait() { asm volatile("cp.async.wait_group %0;" :: "n"(N) : "memory"); }
typedef unsigned long long u64t;
__device__ __forceinline__ void mma16(float* c, const uint32_t* a, uint32_t b0, uint32_t b1) {
    asm volatile(
        "mma.sync.aligned.m16n8k16.row.col.f32.bf16.bf16.f32 "
        "{%0,%1,%2,%3}, {%4,%5,%6,%7}, {%8,%9}, {%0,%1,%2,%3};"
        : "+f"(c[0]), "+f"(c[1]), "+f"(c[2]), "+f"(c[3])
        : "r"(a[0]), "r"(a[1]), "r"(a[2]), "r"(a[3]), "r"(b0), "r"(b1));
}

// ---------------- merged weight pre-pack (single launch) ----------------
__device__ __forceinline__ void pack_seg(const float* __restrict__ W, uint2* __restrict__ dst,
                                         int K, int N, int idx) {
    int kp2 = K >> 1;
    int n = idx / kp2, kp = idx - n * kp2;
    int chunk = n >> 7, nn = n & 127;
    dst[((size_t)chunk * 128 + nn) * kp2 + kp] =
        pack_bf16_pair(W[(size_t)(2 * kp) * N + n], W[(size_t)(2 * kp + 1) * N + n]);
}
__global__ void __launch_bounds__(256) pack_all(const float* __restrict__ wqkv,
                                                const float* __restrict__ wo,
                                                const float* __restrict__ ffw1,
                                                const float* __restrict__ ffw2,
                                                const float* __restrict__ cw2,
                                                const float* __restrict__ sw1,
                                                uint2* __restrict__ gw) {
    int idx = blockIdx.x * 256 + threadIdx.x;
    if (idx < 49152) {
        int l = idx / 24576, r = idx - l * 24576;
        pack_seg(wqkv + (size_t)l * 49152, gw + (l ? OFF_QKV1 : OFF_QKV0), 128, 384, r);
    } else if (idx < 65536) {
        int r = idx - 49152;
        int l = r / 8192; r -= l * 8192;
        pack_seg(wo + (size_t)l * 16384, gw + (l ? OFF_WO1 : OFF_WO0), 128, 128, r);
    } else if (idx < 98304) {
        int r = idx - 65536;
        int l = r / 16384; r -= l * 16384;
        pack_seg(ffw1 + (size_t)l * 32768, gw + (l ? OFF_FF11 : OFF_FF10), 128, 256, r);
    } else if (idx < 131072) {
        int r = idx - 98304;
        int l = r / 16384; r -= l * 16384;
        pack_seg(ffw2 + (size_t)l * 32768, gw + (l ? OFF_FF21 : OFF_FF20), 256, 128, r);
    } else if (idx < 135168) {
        pack_seg(cw2, gw + OFF_CW2, 64, 128, idx - 131072);
    } else if (idx < 200704) {
        int r = idx - 135168;
        int n = r / 128, kp = r - (r / 128) * 128;
        int chunk = n >> 7, nn = n & 127;
        float v0 = sw1[((size_t)(n >> 7) * 258 + 2 + 2 * kp) * 128 + nn];
        float v1 = sw1[((size_t)(n >> 7) * 258 + 2 + 2 * kp + 1) * 128 + nn];
        gw[OFF_SW1 + ((size_t)chunk * 128 + nn) * 128 + kp] = pack_bf16_pair(v0, v1);
    }
}

// ---------------- streaming bf16 2-term GEMM ----------------
// MODE: 0 bias fp32-only, 1 relu pack-only, 2 res(pack)+LN pack-only, 3 silu pack-only, 5 bias pack-only
#define RS 20
#define TBUF 20480
#define TG_SMEM (4 * TBUF)
template <int MODE>
__global__ void __launch_bounds__(128, 2) tgemm(const uint2* __restrict__ Apack,
                                                const uint2* __restrict__ Bpack,
                                                int Ktot,
                                                const float* __restrict__ bias,
                                                const uint2* __restrict__ respack,
                                                const float* __restrict__ gma,
                                                const float* __restrict__ bta,
                                                float* __restrict__ C, int ldc,
                                                uint2* __restrict__ Cpack, int ldcp) {
    extern __shared__ char dsm[];
    const uint32_t sbase = smem_u32(dsm);
    const int t = threadIdx.x;
    const int w = t >> 5, lane = t & 31;
    const int g = lane >> 2, t4 = lane & 3;
    const int bn = blockIdx.x * 128, bm = blockIdx.y * 128;
    const int wrow = w * 32;
    const int kpTot = Ktot >> 1;

    float acc0[16][4], acc1[16][4];
#pragma unroll
    for (int j = 0; j < 16; j++)
#pragma unroll
        for (int q = 0; q < 4; q++) { acc0[j][q] = 0.f; acc1[j][q] = 0.f; }

    const int P = Ktot >> 5;
    const uint2* Bbase = Bpack + (size_t)blockIdx.x * 128 * kpTot;
    const int srow = t >> 3, sj = t & 7;

#pragma unroll
    for (int i = 0; i < 8; i++) {
        int row = srow + i * 16;
        cp16(sbase + (uint32_t)(row * RS * 8 + sj * 16),
             Apack + (size_t)(bm + row) * kpTot + sj * 2);
        cp16(sbase + (uint32_t)(2 * TBUF + row * RS * 8 + sj * 16),
             Bbase + (size_t)row * kpTot + sj * 2);
    }
    cp_commit();

    for (int p = 0; p < P; p++) {
        const bool more = (p + 1 < P);
        if (more) {
            const int buf = (p + 1) & 1;
            const int kpo = (p + 1) * 16;
#pragma unroll
            for (int i = 0; i < 8; i++) {
                int row = srow + i * 16;
                cp16(sbase + (uint32_t)(buf * TBUF + row * RS * 8 + sj * 16),
                     Apack + (size_t)(bm + row) * kpTot + kpo + sj * 2);
                cp16(sbase + (uint32_t)(2 * TBUF + buf * TBUF + row * RS * 8 + sj * 16),
                     Bbase + (size_t)row * kpTot + kpo + sj * 2);
            }
            cp_commit();
            cp_wait<1>();
        } else {
            cp_wait<0>();
        }
        __syncthreads();

        const uint2* As = (const uint2*)(dsm + (p & 1) * TBUF);
        const uint2* Bs = (const uint2*)(dsm + 2 * TBUF + (p & 1) * TBUF);
#pragma unroll
        for (int h2 = 0; h2 < 2; h2++) {
            const int kb = h2 * 8;
            const int r = wrow + g;
            uint32_t a0h[4], a0l[4], a1h[4], a1l[4];
            uint2 q;
            q = As[(r) * RS + kb + t4];          a0h[0] = q.x; a0l[0] = q.y;
            q = As[(r + 8) * RS + kb + t4];      a0h[1] = q.x; a0l[1] = q.y;
            q = As[(r) * RS + kb + t4 + 4];      a0h[2] = q.x; a0l[2] = q.y;
            q = As[(r + 8) * RS + kb + t4 + 4];  a0h[3] = q.x; a0l[3] = q.y;
            q = As[(r + 16) * RS + kb + t4];     a1h[0] = q.x; a1l[0] = q.y;
            q = As[(r + 24) * RS + kb + t4];     a1h[1] = q.x; a1l[1] = q.y;
            q = As[(r + 16) * RS + kb + t4 + 4]; a1h[2] = q.x; a1l[2] = q.y;
            q = As[(r + 24) * RS + kb + t4 + 4]; a1h[3] = q.x; a1l[3] = q.y;
#pragma unroll
            for (int j = 0; j < 16; j++) {
                uint2 b0 = Bs[(j * 8 + g) * RS + kb + t4];
                uint2 b1 = Bs[(j * 8 + g) * RS + kb + t4 + 4];
                mma16(acc0[j], a0h, b0.x, b1.x);
                mma16(acc0[j], a0l, b0.x, b1.x);
                mma16(acc0[j], a0h, b0.y, b1.y);
                mma16(acc1[j], a1h, b0.x, b1.x);
                mma16(acc1[j], a1l, b0.x, b1.x);
                mma16(acc1[j], a1h, b0.y, b1.y);
            }
        }
        __syncthreads();
    }

    float2 bias2[16];
#pragma unroll
    for (int j = 0; j < 16; j++) bias2[j] = *(const float2*)(bias + bn + j * 8 + 2 * t4);

    if (MODE == 2) {
#pragma unroll
        for (int i = 0; i < 2; i++) {
            float (*ac)[4] = i ? acc1 : acc0;
#pragma unroll
            for (int h = 0; h < 2; h++) {
                const int row = bm + wrow + i * 16 + h * 8 + g;
                const uint2* rp = respack + (size_t)row * 64 + t4;
                float sum = 0.f;
#pragma unroll
                for (int j = 0; j < 16; j++) {
                    float2 rv = unpack_pair(rp[4 * j]);
                    float v0 = ac[j][2 * h] + bias2[j].x + rv.x;
                    float v1 = ac[j][2 * h + 1] + bias2[j].y + rv.y;
                    ac[j][2 * h] = v0;
                    ac[j][2 * h + 1] = v1;
                    sum += v0 + v1;
                }
                sum += __shfl_xor_sync(0xffffffffu, sum, 1);
                sum += __shfl_xor_sync(0xffffffffu, sum, 2);
                const float mean = sum * (1.f / 128.f);
                float var = 0.f;
#pragma unroll
                for (int j = 0; j < 16; j++) {
                    float v0 = ac[j][2 * h] - mean;
                    float v1 = ac[j][2 * h + 1] - mean;
                    ac[j][2 * h] = v0;
                    ac[j][2 * h + 1] = v1;
                    var += v0 * v0 + v1 * v1;
                }
                var += __shfl_xor_sync(0xffffffffu, var, 1);
                var += __shfl_xor_sync(0xffffffffu, var, 2);
                const float rs = rsqrtf(var * (1.f / 128.f) + 1e-5f);
                uint2* pp = Cpack + (size_t)row * ldcp + t4;
#pragma unroll
                for (int j = 0; j < 16; j++) {
                    float2 gv = *(const float2*)(gma + j * 8 + 2 * t4);
                    float2 tv = *(const float2*)(bta + j * 8 + 2 * t4);
                    float o0 = fmaf(gv.x, ac[j][2 * h] * rs, tv.x);
                    float o1 = fmaf(gv.y, ac[j][2 * h + 1] * rs, tv.y);
                    pp[4 * j] = pack_bf16_pair(o0, o1);
                }
            }
        }
    } else {
#pragma unroll
        for (int i = 0; i < 2; i++) {
            float (*ac)[4] = i ? acc1 : acc0;
#pragma unroll
            for (int h = 0; h < 2; h++) {
                const int row = bm + wrow + i * 16 + h * 8 + g;
                float* cp = (MODE == 0) ? (C + (size_t)row * ldc + bn + 2 * t4) : nullptr;
                uint2* pp = (MODE != 0) ? (Cpack + (size_t)row * ldcp + (bn >> 1) + t4) : nullptr;
#pragma unroll
                for (int j = 0; j < 16; j++) {
                    float o0 = ac[j][2 * h] + bias2[j].x;
                    float o1 = ac[j][2 * h + 1] + bias2[j].y;
                    if (MODE == 1) { o0 = fmaxf(o0, 0.f); o1 = fmaxf(o1, 0.f); }
                    if (MODE == 3) { o0 = siluf(o0); o1 = siluf(o1); }
                    if (MODE == 0) { cp[j * 8] = o0; cp[j * 8 + 1] = o1; }
                    else pp[4 * j] = pack_bf16_pair(o0, o1);
                }
            }
        }
    }
}

// ---------------- time embedding ----------------
__global__ void __launch_bounds__(256) time_kernel(const int* __restrict__ ts,
                                                   const float* __restrict__ w1,
                                                   const float* __restrict__ b1,
                                                   const float* __restrict__ w2,
                                                   const float* __restrict__ b2) {
    __shared__ float te[128];
    __shared__ float hid[256];
    __shared__ float tout[128];
    const int b = blockIdx.x, t = threadIdx.x;
    const float tf = (float)ts[b];
    if (t < 128) {
        int i = t & 63;
        float freq = expf(-0.14391156831212787f * (float)i);
        float arg = tf * freq;
        te[t] = (t < 64) ? cosf(arg) : sinf(arg);
    }
    __syncthreads();
    float a = b1[t];
    for (int i = 0; i < 128; i++) a = fmaf(te[i], w1[i * 256 + t], a);
    hid[t] = siluf(a);
    __syncthreads();
    if (t < 128) {
        float a2 = b2[t];
        for (int i = 0; i < 256; i++) a2 = fmaf(hid[i], w2[i * 128 + t], a2);
        g_comb[(size_t)b * 256 + t] = a2;
        tout[t] = a2;
    }
    __syncthreads();
    if (t < 64) g_comb_pack[(size_t)b * 128 + t] = pack_bf16_pair(tout[2 * t], tout[2 * t + 1]);
}

// ---------------- cond layer1 -> packed ----------------
__global__ void __launch_bounds__(256) condh1_kernel(const float* __restrict__ cond,
                                                     const float* __restrict__ w1,
                                                     const float* __restrict__ b1,
                                                     uint2* __restrict__ outp) {
    const size_t row = (size_t)blockIdx.x * 32 + (threadIdx.x >> 3);
    const int dg = threadIdx.x & 7;
    const float* cp = cond + row * 6;
    float c0 = cp[0], c1 = cp[1], c2 = cp[2], c3 = cp[3], c4 = cp[4], c5 = cp[5];
    float o[8];
#pragma unroll
    for (int j = 0; j < 8; j++) {
        int dd = dg * 8 + j;
        float a = b1[dd];
        a = fmaf(c0, w1[0 * 64 + dd], a);
        a = fmaf(c1, w1[1 * 64 + dd], a);
        a = fmaf(c2, w1[2 * 64 + dd], a);
        a = fmaf(c3, w1[3 * 64 + dd], a);
        a = fmaf(c4, w1[4 * 64 + dd], a);
        a = fmaf(c5, w1[5 * 64 + dd], a);
        o[j] = siluf(a);
    }
#pragma unroll
    for (int i = 0; i < 4; i++)
        outp[row * 32 + dg * 4 + i] = pack_bf16_pair(o[2 * i], o[2 * i + 1]);
}

// ---------------- attention: bf16 MMA, per (b,head) CTA ----------------
#define ATTN_SMEM (3 * 20480 + 32 * 66 * 8)   // 78336
__global__ void __launch_bounds__(128, 2) attn_kernel(const uint2* __restrict__ qkvp) {
    extern __shared__ char sm[];
    uint2* Qp = (uint2*)sm;
    uint2* Kp = (uint2*)(sm + 20480);
    uint2* Vp = (uint2*)(sm + 40960);
    uint2* Vt = (uint2*)(sm + 61440);
    const uint32_t sb = smem_u32(sm);
    const int b = blockIdx.x >> 2, hd = blockIdx.x & 3;
    const int t = threadIdx.x, w = t >> 5, lane = t & 31;
    const int g = lane >> 2, t4 = lane & 3;
    const int wrow = w * 32;
    const int srow = t >> 3, sj = t & 7;
    const uint2* base = qkvp + (size_t)(b * 128) * 192;

#pragma unroll
    for (int i = 0; i < 8; i++) {
        int row = srow + i * 16;
        const uint2* rp = base + (size_t)row * 192;
        cp16(sb + (uint32_t)((row * RS + sj * 2) * 8), rp + hd * 16 + sj * 2);
        cp16(sb + 20480u + (uint32_t)((row * RS + sj * 2) * 8), rp + 64 + hd * 16 + sj * 2);
        cp16(sb + 40960u + (uint32_t)((row * RS + sj * 2) * 8), rp + 128 + hd * 16 + sj * 2);
    }
    cp_commit();
    cp_wait<0>();
    __syncthreads();

    for (int e = t; e < 32 * 64; e += 128) {
        int d = e >> 6, kp = e & 63;
        uint2 p0 = Vp[(2 * kp) * RS + (d >> 1)];
        uint2 p1 = Vp[(2 * kp + 1) * RS + (d >> 1)];
        float v0, v1;
        if (d & 1) {
            v0 = __uint_as_float(p0.x & 0xffff0000u) + __uint_as_float(p0.y & 0xffff0000u);
            v1 = __uint_as_float(p1.x & 0xffff0000u) + __uint_as_float(p1.y & 0xffff0000u);
        } else {
            v0 = __uint_as_float(p0.x << 16) + __uint_as_float(p0.y << 16);
            v1 = __uint_as_float(p1.x << 16) + __uint_as_float(p1.y << 16);
        }
        Vt[d * 66 + kp] = pack_bf16_pair(v0, v1);
    }
    __syncthreads();

    const float cs = 0.17677669529663687f;

#pragma unroll
    for (int tile = 0; tile < 2; tile++) {
        float acc[16][4];
#pragma unroll
        for (int j = 0; j < 16; j++)
#pragma unroll
            for (int q = 0; q < 4; q++) acc[j][q] = 0.f;
        const int r = wrow + tile * 16 + g;

#pragma unroll
        for (int h2 = 0; h2 < 2; h2++) {
            const int kb = h2 * 8;
            uint32_t ah[4], al[4];
            uint2 q;
            q = Qp[r * RS + kb + t4];           ah[0] = q.x; al[0] = q.y;
            q = Qp[(r + 8) * RS + kb + t4];     ah[1] = q.x; al[1] = q.y;
            q = Qp[r * RS + kb + t4 + 4];       ah[2] = q.x; al[2] = q.y;
            q = Qp[(r + 8) * RS + kb + t4 + 4]; ah[3] = q.x; al[3] = q.y;
#pragma unroll
            for (int j = 0; j < 16; j++) {
                uint2 b0 = Kp[(j * 8 + g) * RS + kb + t4];
                uint2 b1 = Kp[(j * 8 + g) * RS + kb + t4 + 4];
                mma16(acc[j], ah, b0.x, b1.x);
                mma16(acc[j], al, b0.x, b1.x);
                mma16(acc[j], ah, b0.y, b1.y);
            }
        }

        float m0 = -1e30f, m1 = -1e30f;
#pragma unroll
        for (int j = 0; j < 16; j++) {
            m0 = fmaxf(m0, fmaxf(acc[j][0], acc[j][1]));
            m1 = fmaxf(m1, fmaxf(acc[j][2], acc[j][3]));
        }
        m0 = fmaxf(m0, __shfl_xor_sync(0xffffffffu, m0, 1));
        m0 = fmaxf(m0, __shfl_xor_sync(0xffffffffu, m0, 2));
        m1 = fmaxf(m1, __shfl_xor_sync(0xffffffffu, m1, 1));
        m1 = fmaxf(m1, __shfl_xor_sync(0xffffffffu, m1, 2));
        float l0 = 0.f, l1 = 0.f;
#pragma unroll
        for (int j = 0; j < 16; j++) {
            acc[j][0] = __expf((acc[j][0] - m0) * cs);
            acc[j][1] = __expf((acc[j][1] - m0) * cs);
            acc[j][2] = __expf((acc[j][2] - m1) * cs);
            acc[j][3] = __expf((acc[j][3] - m1) * cs);
            l0 += acc[j][0] + acc[j][1];
            l1 += acc[j][2] + acc[j][3];
        }
        l0 += __shfl_xor_sync(0xffffffffu, l0, 1);
        l0 += __shfl_xor_sync(0xffffffffu, l0, 2);
        l1 += __shfl_xor_sync(0xffffffffu, l1, 1);
        l1 += __shfl_xor_sync(0xffffffffu, l1, 2);
        const float li0 = 1.f / l0, li1 = 1.f / l1;

        float o[4][4];
#pragma unroll
        for (int j = 0; j < 4; j++)
#pragma unroll
            for (int q = 0; q < 4; q++) o[j][q] = 0.f;
#pragma unroll
        for (int kc = 0; kc < 8; kc++) {
            uint32_t ph[4], pl[4];
            uint2 u;
            u = pack_bf16_pair(acc[2 * kc][0], acc[2 * kc][1]);         ph[0] = u.x; pl[0] = u.y;
            u = pack_bf16_pair(acc[2 * kc][2], acc[2 * kc][3]);         ph[1] = u.x; pl[1] = u.y;
            u = pack_bf16_pair(acc[2 * kc + 1][0], acc[2 * kc + 1][1]); ph[2] = u.x; pl[2] = u.y;
            u = pack_bf16_pair(acc[2 * kc + 1][2], acc[2 * kc + 1][3]); ph[3] = u.x; pl[3] = u.y;
#pragma unroll
            for (int j = 0; j < 4; j++) {
                uint2 b0 = Vt[(j * 8 + g) * 66 + kc * 8 + t4];
                uint2 b1 = Vt[(j * 8 + g) * 66 + kc * 8 + t4 + 4];
                mma16(o[j], ph, b0.x, b1.x);
                mma16(o[j], pl, b0.x, b1.x);
                mma16(o[j], ph, b0.y, b1.y);
            }
        }

        const int row0 = b * 128 + r;
        uint2* p0 = g_attn_pack + (size_t)row0 * 64 + hd * 16 + t4;
        uint2* p1 = g_attn_pack + (size_t)(row0 + 8) * 64 + hd * 16 + t4;
#pragma unroll
        for (int j = 0; j < 4; j++) {
            p0[j * 4] = pack_bf16_pair(o[j][0] * li0, o[j][1] * li0);
            p1[j * 4] = pack_bf16_pair(o[j][2] * li1, o[j][3] * li1);
        }
    }
}

// ---------------- mean pool (reads pack) ----------------
__global__ void __launch_bounds__(128) pool_kernel() {
    __shared__ float buf[128];
    const int b = blockIdx.x, d = threadIdx.x;
    const uint2* p = g_h_pack + (size_t)b * 128 * 64 + (d >> 1);
    float s = 0.f;
    if (d & 1) {
        for (int j = 0; j < 128; j++) {
            uint2 v = p[(size_t)j * 64];
            s += __uint_as_float(v.x & 0xffff0000u) + __uint_as_float(v.y & 0xffff0000u);
        }
    } else {
        for (int j = 0; j < 128; j++) {
            uint2 v = p[(size_t)j * 64];
            s += __uint_as_float(v.x << 16) + __uint_as_float(v.y << 16);
        }
    }
    s *= (1.f / 128.f);
    g_comb[(size_t)b * 256 + 128 + d] = s;
    buf[d] = s;
    __syncthreads();
    if (d < 64) g_comb_pack[(size_t)b * 128 + 64 + d] = pack_bf16_pair(buf[2 * d], buf[2 * d + 1]);
}

// ---------------- mixture weights ----------------
__global__ void __launch_bounds__(128) mw_kernel(const float* __restrict__ w1,
                                                 const float* __restrict__ b1,
                                                 const float* __restrict__ w2,
                                                 const float* __restrict__ b2) {
    __shared__ float scm[256];
    __shared__ float hid[128];
    __shared__ float lg[4];
    const int b = blockIdx.x, t = threadIdx.x;
    scm[t] = g_comb[(size_t)b * 256 + t];
    scm[128 + t] = g_comb[(size_t)b * 256 + 128 + t];
    __syncthreads();
    float a = b1[t];
    for (int i = 0; i < 256; i++) a = fmaf(scm[i], w1[i * 128 + t], a);
    hid[t] = siluf(a);
    __syncthreads();
    if (t < 4) {
        float a2 = b2[t];
        for (int j = 0; j < 128; j++) a2 = fmaf(hid[j], w2[j * 4 + t], a2);
        lg[t] = a2;
    }
    __syncthreads();
    if (t == 0) {
        float mm = fmaxf(fmaxf(lg[0], lg[1]), fmaxf(lg[2], lg[3]));
        float e0 = __expf(lg[0] - mm), e1 = __expf(lg[1] - mm);
        float e2 = __expf(lg[2] - mm), e3 = __expf(lg[3] - mm);
        float inv = 1.f / (e0 + e1 + e2 + e3);
        g_mw[(size_t)b * 4 + 0] = e0 * inv;
        g_mw[(size_t)b * 4 + 1] = e1 * inv;
        g_mw[(size_t)b * 4 + 2] = e2 * inv;
        g_mw[(size_t)b * 4 + 3] = e3 * inv;
    }
}

// ---------------- students ----------------
__global__ void __launch_bounds__(128) student_kernel(const float* __restrict__ x,
                                                      const float* __restrict__ sw1,
                                                      const float* __restrict__ sw2,
                                                      const float* __restrict__ sb2,
                                                      float* __restrict__ out) {
    __shared__ float sb[512], w0[512], w1s[512], s2a[512], s2b[512];
    __shared__ float smw[4], sbias2[8];
    const int b = blockIdx.x, t = threadIdx.x;
    for (int i = t; i < 512; i += 128) {
        sb[i] = g_base[(size_t)b * 512 + i];
        int k = i >> 7, j = i & 127;
        w0[i] = sw1[((size_t)k * 258 + 0) * 128 + j];
        w1s[i] = sw1[((size_t)k * 258 + 1) * 128 + j];
        s2a[i] = sw2[i * 2 + 0];
        s2b[i] = sw2[i * 2 + 1];
    }
    if (t < 4) smw[t] = g_mw[(size_t)b * 4 + t];
    if (t < 8) sbias2[t] = sb2[t];
    __syncthreads();
    const float x0 = x[(size_t)b * 256 + t];
    const float x1 = x[(size_t)b * 256 + 128 + t];
    float o0 = 0.f, o1 = 0.f;
#pragma unroll
    for (int k = 0; k < 4; k++) {
        float a0 = 0.f, a1 = 0.f;
        for (int j = 0; j < 128; j++) {
            int idx = k * 128 + j;
            float hv = tanh_fast(fmaf(x1, w1s[idx], fmaf(x0, w0[idx], sb[idx])));
            a0 = fmaf(hv, s2a[idx], a0);
            a1 = fmaf(hv, s2b[idx], a1);
        }
        float wk = smw[k];
        o0 = fmaf(wk, a0 + sbias2[k * 2 + 0], o0);
        o1 = fmaf(wk, a1 + sbias2[k * 2 + 1], o1);
    }
    out[(size_t)b * 256 + t] = o0;
    out[(size_t)b * 256 + 128 + t] = o1;
}

// ---------------- launcher ----------------
extern "C" void kernel_launch(void* const* d_in, const int* in_sizes, int n_in,
                              void* d_out, int out_size) {
    const float* x    = (const float*)d_in[0];
    const int*   ts   = (const int*)d_in[1];
    const float* cond = (const float*)d_in[2];
    const float* t_w1 = (const float*)d_in[3];
    const float* t_b1 = (const float*)d_in[4];
    const float* t_w2 = (const float*)d_in[5];
    const float* t_b2 = (const float*)d_in[6];
    const float* c_w1 = (const float*)d_in[7];
    const float* c_b1 = (const float*)d_in[8];
    const float* c_w2 = (const float*)d_in[9];
    const float* c_b2 = (const float*)d_in[10];
    const float* wqkv = (const float*)d_in[11];
    const float* bqkv = (const float*)d_in[12];
    const float* wo   = (const float*)d_in[13];
    const float* bo   = (const float*)d_in[14];
    const float* ln1g = (const float*)d_in[15];
    const float* ln1b = (const float*)d_in[16];
    const float* ffw1 = (const float*)d_in[17];
    const float* ffb1 = (const float*)d_in[18];
    const float* ffw2 = (const float*)d_in[19];
    const float* ffb2 = (const float*)d_in[20];
    const float* ln2g = (const float*)d_in[21];
    const float* ln2b = (const float*)d_in[22];
    const float* mww1 = (const float*)d_in[23];
    const float* mwb1 = (const float*)d_in[24];
    const float* mww2 = (const float*)d_in[25];
    const float* mwb2 = (const float*)d_in[26];
    const float* sw1  = (const float*)d_in[27];
    const float* sb1  = (const float*)d_in[28];
    const float* sw2  = (const float*)d_in[29];
    const float* sb2  = (const float*)d_in[30];
    float* out = (float*)d_out;

    float *gqkv, *gcomb, *gbase;
    uint2 *ghp, *gap, *gcmb, *gw;
    cudaGetSymbolAddress((void**)&gqkv, g_qkv);
    cudaGetSymbolAddress((void**)&gcomb, g_comb);
    cudaGetSymbolAddress((void**)&gbase, g_base);
    cudaGetSymbolAddress((void**)&ghp, g_h_pack);
    cudaGetSymbolAddress((void**)&gap, g_attn_pack);
    cudaGetSymbolAddress((void**)&gcmb, g_comb_pack);
    cudaGetSymbolAddress((void**)&gw, g_wp);
    uint2* gqp = (uint2*)gqkv;   // qkv pack [row][192]
    uint2* gfp = (uint2*)gqkv;   // ffn-hidden pack [row][128] (after attn consumed qkv pack)
    uint2* gcp = gap;            // cond-hidden pack aliases attn pack

    cudaFuncSetAttribute(attn_kernel, cudaFuncAttributeMaxDynamicSharedMemorySize, ATTN_SMEM);
    cudaFuncSetAttribute(tgemm<0>, cudaFuncAttributeMaxDynamicSharedMemorySize, TG_SMEM);
    cudaFuncSetAttribute(tgemm<1>, cudaFuncAttributeMaxDynamicSharedMemorySize, TG_SMEM);
    cudaFuncSetAttribute(tgemm<2>, cudaFuncAttributeMaxDynamicSharedMemorySize, TG_SMEM);
    cudaFuncSetAttribute(tgemm<3>, cudaFuncAttributeMaxDynamicSharedMemorySize, TG_SMEM);
    cudaFuncSetAttribute(tgemm<5>, cudaFuncAttributeMaxDynamicSharedMemorySize, TG_SMEM);

    pack_all<<<784, 256>>>(wqkv, wo, ffw1, ffw2, c_w2, sw1, gw);
    time_kernel<<<B_, 256>>>(ts, t_w1, t_b1, t_w2, t_b2);
    condh1_kernel<<<MROWS / 32, 256>>>(cond, c_w1, c_b1, gcp);
    // cond layer2: silu -> ghp (pack only)
    tgemm<3><<<dim3(1, MROWS / 128), 128, TG_SMEM>>>(gcp, gw + OFF_CW2, 64, c_b2,
                                                     nullptr, nullptr, nullptr,
                                                     nullptr, 0, ghp, 64);
    const size_t qkvoff[2] = {OFF_QKV0, OFF_QKV1};
    const size_t wooff[2] = {OFF_WO0, OFF_WO1};
    const size_t f1off[2] = {OFF_FF10, OFF_FF11};
    const size_t f2off[2] = {OFF_FF20, OFF_FF21};
    for (int l = 0; l < 2; l++) {
        // qkv: pack-only output [row][192]
        tgemm<5><<<dim3(3, MROWS / 128), 128, TG_SMEM>>>(ghp, gw + qkvoff[l], 128,
                                                         bqkv + l * 384, nullptr, nullptr,
                                                         nullptr, nullptr, 0, gqp, 192);
        attn_kernel<<<B_ * 4, 128, ATTN_SMEM>>>(gqp);
        // o-proj + res(pack) + LN -> ghp
        tgemm<2><<<dim3(1, MROWS / 128), 128, TG_SMEM>>>(gap, gw + wooff[l], 128,
                                                         bo + l * 128, ghp, ln1g + l * 128,
                                                         ln1b + l * 128, nullptr, 0, ghp, 64);
        // ffn1 relu -> pack (into dead qkv-pack region)
        tgemm<1><<<dim3(2, MROWS / 128), 128, TG_SMEM>>>(ghp, gw + f1off[l], 128,
                                                         ffb1 + l * 256, nullptr, nullptr,
                                                         nullptr, nullptr, 0, gfp, 128);
        // ffn2 (K=256) + res(pack) + LN -> ghp
        tgemm<2><<<dim3(1, MROWS / 128), 128, TG_SMEM>>>(gfp, gw + f2off[l], 256,
                                                         ffb2 + l * 128, ghp, ln2g + l * 128,
                                                         ln2b + l * 128, nullptr, 0, ghp, 64);
    }
    pool_kernel<<<B_, 128>>>();
    mw_kernel<<<B_, 128>>>(mww1, mwb1, mww2, mwb2);
    tgemm<0><<<dim3(4, B_ / 128), 128, TG_SMEM>>>(gcmb, gw + OFF_SW1, 256, sb1,
                                                  nullptr, nullptr, nullptr,
                                                  gbase, 512, nullptr, 0);
    student_kernel<<<B_, 128>>>(x, sw1, sw2, sb2, out);
}